// round 10
// baseline (speedup 1.0000x reference)
#include <cuda_runtime.h>
#include <cuda_bf16.h>

#define NLAY 256
#define TSTEPS 64
#define BATCH 4
#define HDIM 256
#define GDIM 768
#define NCLS 26

// Packed transposed bf16-pair weights: [m][(l*128 + kp)*768 + g], u32 = (bf16 k even | bf16 k odd<<16)
// m: 0=enc_ih 1=enc_hh 2=dec_ih 3=dec_hh
__device__ unsigned g_wpack[4][(size_t)NLAY * 128 * GDIM];
// Sequence slots: enc pass: block l reads slot l, writes slot l+1 (slot 256 = relu'd emb).
// dec pass: block 0 reads slot 256, block l writes slot l (slot 255 = hid).
__device__ float g_seq[NLAY + 1][TSTEPS][BATCH][HDIM];
__device__ int g_flags[2 * NLAY];

typedef unsigned long long u64;

__device__ __forceinline__ u64 pk2(float lo, float hi) {
    u64 r; asm("mov.b64 %0,{%1,%2};" : "=l"(r) : "f"(lo), "f"(hi)); return r;
}
__device__ __forceinline__ void unpk2(u64 v, float& lo, float& hi) {
    asm("mov.b64 {%0,%1},%2;" : "=f"(lo), "=f"(hi) : "l"(v));
}
__device__ __forceinline__ u64 duplo(unsigned u) {
    float f = __uint_as_float(u << 16);
    u64 r; asm("mov.b64 %0,{%1,%1};" : "=l"(r) : "f"(f)); return r;
}
__device__ __forceinline__ u64 duphi(unsigned u) {
    float f = __uint_as_float(u & 0xffff0000u);
    u64 r; asm("mov.b64 %0,{%1,%1};" : "=l"(r) : "f"(f)); return r;
}
__device__ __forceinline__ void fma2(u64& acc, u64 a, u64 b) {
    asm("fma.rn.f32x2 %0,%1,%2,%0;" : "+l"(acc) : "l"(a), "l"(b));
}

__global__ void zero_flags_kernel() { g_flags[threadIdx.x] = 0; }

// Both convs are pointwise -> seq[0][t][b][h] = X[b,0,2t]*A[h] + C[h]
__global__ void conv_front_kernel(const float* __restrict__ X,
                                  const float* __restrict__ c1w,
                                  const float* __restrict__ c1b,
                                  const float* __restrict__ c2w,
                                  const float* __restrict__ c2b) {
    __shared__ float xs[512];
    int j = threadIdx.x;
    xs[j] = X[j];
    xs[256 + j] = X[256 + j];
    __syncthreads();
    float A = 0.f, C = 0.f;
    for (int c = 0; c < 128; ++c) {
        float w2 = c2w[j * 128 + c];
        A += w2 * c1w[c];
        C += w2 * c1b[c];
    }
    C += c2b[j];
    for (int t = 0; t < TSTEPS; ++t)
        for (int b = 0; b < BATCH; ++b)
            g_seq[0][t][b][j] = xs[b * 128 + 2 * t] * A + C;
}

// Repack fp32 [l][g][k] -> bf16-pair u32 [(l*128+kp)*768+g], tiled transpose in smem.
// grid = 4 * 256 * 12 * 4 blocks of 256 threads.
__global__ void pack_weights_kernel(const float* __restrict__ eih,
                                    const float* __restrict__ ehh,
                                    const float* __restrict__ dih,
                                    const float* __restrict__ dhh) {
    __shared__ float tile[64][65];
    int bid = blockIdx.x;
    int m = bid / 12288;
    int r = bid % 12288;
    int l = r / 48;
    int r2 = r % 48;
    int gt = r2 / 4;   // g tile (64 wide), 0..11
    int kt = r2 % 4;   // k tile (64 wide), 0..3
    const float* src = (m == 0) ? eih : (m == 1) ? ehh : (m == 2) ? dih : dhh;
    int tid = threadIdx.x;
    #pragma unroll
    for (int i = 0; i < 16; ++i) {
        int idx = tid + i * 256;
        int gg = idx >> 6, kk = idx & 63;
        tile[gg][kk] = src[((size_t)l * GDIM + gt * 64 + gg) * HDIM + kt * 64 + kk];
    }
    __syncthreads();
    #pragma unroll
    for (int i = 0; i < 8; ++i) {
        int o = tid + i * 256;
        int gg = o & 63, kp = o >> 6;   // kp 0..31 local
        float f0 = tile[gg][2 * kp];
        float f1 = tile[gg][2 * kp + 1];
        unsigned u = (unsigned)__bfloat16_as_ushort(__float2bfloat16(f0)) |
                     ((unsigned)__bfloat16_as_ushort(__float2bfloat16(f1)) << 16);
        g_wpack[m][((size_t)l * 128 + kt * 32 + kp) * GDIM + gt * 64 + gg] = u;
    }
}

// Wavefront GRU stack: block l = layer l, thread j = hidden unit j (all 4 batches).
__global__ void __launch_bounds__(256)
gru_wave_kernel(const float* __restrict__ bih_all,
                const float* __restrict__ bhh_all,
                int pass) {
    const int l = blockIdx.x;
    const int j = threadIdx.x;

    __shared__ __align__(16) u64 xsm[2 * HDIM];       // [pair(b01/b23)][k]
    __shared__ __align__(16) u64 hsm[2][2 * HDIM];    // double buffered

    const unsigned* __restrict__ wih0 = &g_wpack[2 * pass][(size_t)l * 128 * GDIM + j];
    const unsigned* __restrict__ whh0 = &g_wpack[2 * pass + 1][(size_t)l * 128 * GDIM + j];

    const float bxr = bih_all[l * GDIM + j];
    const float bxz = bih_all[l * GDIM + HDIM + j];
    const float bxn = bih_all[l * GDIM + 2 * HDIM + j];
    const float bhr = bhh_all[l * GDIM + j];
    const float bhz = bhh_all[l * GDIM + HDIM + j];
    const float bhn = bhh_all[l * GDIM + 2 * HDIM + j];

    const float* inp = (pass == 0) ? &g_seq[l][0][0][0]
                      : ((l == 0) ? &g_seq[NLAY][0][0][0] : &g_seq[l - 1][0][0][0]);
    float* outp = (pass == 0) ? &g_seq[l + 1][0][0][0] : &g_seq[l][0][0][0];
    const bool relu_out = (pass == 0) && (l == NLAY - 1);
    const int* prevflag = &g_flags[pass * NLAY + l - 1];  // only used if l>0
    int* myflag = &g_flags[pass * NLAY + l];

    hsm[0][j] = 0ull;
    hsm[0][HDIM + j] = 0ull;
    float ho[4] = {0.f, 0.f, 0.f, 0.f};

    int buf = 0;
    for (int t = 0; t < TSTEPS; ++t) {
        if (j == 0 && l > 0) {
            int v;
            do {
                asm volatile("ld.acquire.gpu.global.u32 %0,[%1];"
                             : "=r"(v) : "l"(prevflag) : "memory");
                if (v > t) break;
                __nanosleep(64);
            } while (true);
        }
        __syncthreads();

        {
            const float* xt = inp + t * (BATCH * HDIM);
            float a = xt[j];
            float b = xt[HDIM + j];
            float c = xt[2 * HDIM + j];
            float d = xt[3 * HDIM + j];
            xsm[j]        = pk2(a, b);
            xsm[HDIM + j] = pk2(c, d);
        }
        __syncthreads();

        u64 axr0 = pk2(bxr, bxr), axr1 = axr0;
        u64 axz0 = pk2(bxz, bxz), axz1 = axz0;
        u64 axn0 = pk2(bxn, bxn), axn1 = axn0;
        u64 ahr0 = pk2(bhr, bhr), ahr1 = ahr0;
        u64 ahz0 = pk2(bhz, bhz), ahz1 = ahz0;
        u64 ahn0 = pk2(bhn, bhn), ahn1 = ahn0;

        const u64* hb = hsm[buf];
        const unsigned* wi = wih0;
        const unsigned* wh = whh0;

        #pragma unroll 4
        for (int kp = 0; kp < 128; ++kp) {
            unsigned uri = wi[0], uzi = wi[HDIM], uni = wi[2 * HDIM];
            unsigned urh = wh[0], uzh = wh[HDIM], unh = wh[2 * HDIM];
            ulonglong2 x0v = *(const ulonglong2*)&xsm[2 * kp];
            ulonglong2 x1v = *(const ulonglong2*)&xsm[HDIM + 2 * kp];
            ulonglong2 h0v = *(const ulonglong2*)&hb[2 * kp];
            ulonglong2 h1v = *(const ulonglong2*)&hb[HDIM + 2 * kp];
            u64 w;
            w = duplo(uri); fma2(axr0, w, x0v.x); fma2(axr1, w, x1v.x);
            w = duphi(uri); fma2(axr0, w, x0v.y); fma2(axr1, w, x1v.y);
            w = duplo(uzi); fma2(axz0, w, x0v.x); fma2(axz1, w, x1v.x);
            w = duphi(uzi); fma2(axz0, w, x0v.y); fma2(axz1, w, x1v.y);
            w = duplo(uni); fma2(axn0, w, x0v.x); fma2(axn1, w, x1v.x);
            w = duphi(uni); fma2(axn0, w, x0v.y); fma2(axn1, w, x1v.y);
            w = duplo(urh); fma2(ahr0, w, h0v.x); fma2(ahr1, w, h1v.x);
            w = duphi(urh); fma2(ahr0, w, h0v.y); fma2(ahr1, w, h1v.y);
            w = duplo(uzh); fma2(ahz0, w, h0v.x); fma2(ahz1, w, h1v.x);
            w = duphi(uzh); fma2(ahz0, w, h0v.y); fma2(ahz1, w, h1v.y);
            w = duplo(unh); fma2(ahn0, w, h0v.x); fma2(ahn1, w, h1v.x);
            w = duphi(unh); fma2(ahn0, w, h0v.y); fma2(ahn1, w, h1v.y);
            wi += GDIM; wh += GDIM;
        }

        float xr[4], xz[4], xn[4], hr[4], hz[4], hn[4];
        unpk2(axr0, xr[0], xr[1]); unpk2(axr1, xr[2], xr[3]);
        unpk2(axz0, xz[0], xz[1]); unpk2(axz1, xz[2], xz[3]);
        unpk2(axn0, xn[0], xn[1]); unpk2(axn1, xn[2], xn[3]);
        unpk2(ahr0, hr[0], hr[1]); unpk2(ahr1, hr[2], hr[3]);
        unpk2(ahz0, hz[0], hz[1]); unpk2(ahz1, hz[2], hz[3]);
        unpk2(ahn0, hn[0], hn[1]); unpk2(ahn1, hn[2], hn[3]);

        #pragma unroll
        for (int b = 0; b < 4; ++b) {
            float rg = 1.f / (1.f + __expf(-(xr[b] + hr[b])));
            float zg = 1.f / (1.f + __expf(-(xz[b] + hz[b])));
            float ng = tanhf(xn[b] + rg * hn[b]);
            ho[b] = ng + zg * (ho[b] - ng);       // (1-z)*n + z*h
        }

        hsm[buf ^ 1][j]        = pk2(ho[0], ho[1]);
        hsm[buf ^ 1][HDIM + j] = pk2(ho[2], ho[3]);

        float* ot = outp + t * (BATCH * HDIM);
        #pragma unroll
        for (int b = 0; b < 4; ++b)
            ot[b * HDIM + j] = relu_out ? fmaxf(ho[b], 0.f) : ho[b];

        __syncthreads();                 // all stores done (HB to thread 0)
        if (j == 0) {
            asm volatile("st.release.gpu.global.u32 [%0],%1;"
                         :: "l"(myflag), "r"(t + 1) : "memory");
        }
        buf ^= 1;
    }
}

// Attention + FC + softmax tail. One block per timestep t, 256 threads.
__global__ void attn_fc_kernel(const float* __restrict__ fcl_w,
                               const float* __restrict__ fcl_b,
                               float* __restrict__ out) {
    const int t = blockIdx.x;
    const int tid = threadIdx.x;
    __shared__ float hid_s[BATCH][HDIM];
    __shared__ float sc[BATCH][TSTEPS];
    __shared__ float ctx[BATCH][HDIM];
    __shared__ float lg[BATCH][NCLS];

    #pragma unroll
    for (int b = 0; b < BATCH; ++b)
        hid_s[b][tid] = g_seq[NLAY - 1][t][b][tid];
    __syncthreads();

    // scores[t][b][s] = dot(hid[t,b], emb[s,b]); thread = (s, quarter)
    int s = tid >> 2, q = tid & 3;
    #pragma unroll
    for (int b = 0; b < BATCH; ++b) {
        const float* e = &g_seq[NLAY][s][b][0];
        float acc = 0.f;
        for (int d = q * 64; d < q * 64 + 64; ++d) acc += hid_s[b][d] * e[d];
        acc += __shfl_xor_sync(0xffffffff, acc, 1);
        acc += __shfl_xor_sync(0xffffffff, acc, 2);
        if (q == 0) sc[b][s] = acc;
    }
    __syncthreads();

    if (tid < BATCH) {
        int b = tid;
        float m = -1e30f;
        for (int i = 0; i < TSTEPS; ++i) m = fmaxf(m, sc[b][i]);
        float sum = 0.f;
        for (int i = 0; i < TSTEPS; ++i) { float e = __expf(sc[b][i] - m); sc[b][i] = e; sum += e; }
        float inv = 1.f / sum;
        for (int i = 0; i < TSTEPS; ++i) sc[b][i] *= inv;
    }
    __syncthreads();

    // c = attn0 * emb[0] + sum_{s=0..62} attn[s] * emb[s+1]; thread = d
    #pragma unroll
    for (int b = 0; b < BATCH; ++b) {
        float acc = sc[b][0] * g_seq[NLAY][0][b][tid];
        for (int s2 = 0; s2 < TSTEPS - 1; ++s2)
            acc += sc[b][s2] * g_seq[NLAY][s2 + 1][b][tid];
        ctx[b][tid] = acc;
    }
    __syncthreads();

    if (tid < BATCH * NCLS) {
        int b = tid / NCLS, o = tid % NCLS;
        float acc = fcl_b[o];
        for (int f = 0; f < HDIM; ++f) acc += fcl_w[o * 2 * HDIM + f] * hid_s[b][f];
        for (int f = 0; f < HDIM; ++f) acc += fcl_w[o * 2 * HDIM + HDIM + f] * ctx[b][f];
        lg[b][o] = acc;
    }
    __syncthreads();

    if (tid < BATCH) {
        int b = tid;
        float m = -1e30f;
        for (int o = 0; o < NCLS; ++o) m = fmaxf(m, lg[b][o]);
        float ex[NCLS]; float sum = 0.f;
        for (int o = 0; o < NCLS; ++o) { ex[o] = __expf(lg[b][o] - m); sum += ex[o]; }
        float inv = 1.f / sum;
        for (int o = 0; o < NCLS; ++o)
            out[(t * BATCH + b) * NCLS + o] = ex[o] * inv;
    }
}

extern "C" void kernel_launch(void* const* d_in, const int* in_sizes, int n_in,
                              void* d_out, int out_size) {
    const float* X    = (const float*)d_in[0];
    const float* c1w  = (const float*)d_in[1];
    const float* c1b  = (const float*)d_in[2];
    const float* c2w  = (const float*)d_in[3];
    const float* c2b  = (const float*)d_in[4];
    const float* eih  = (const float*)d_in[5];
    const float* ehh  = (const float*)d_in[6];
    const float* ebih = (const float*)d_in[7];
    const float* ebhh = (const float*)d_in[8];
    const float* dih  = (const float*)d_in[9];
    const float* dhh  = (const float*)d_in[10];
    const float* dbih = (const float*)d_in[11];
    const float* dbhh = (const float*)d_in[12];
    const float* fclw = (const float*)d_in[13];
    const float* fclb = (const float*)d_in[14];
    float* out = (float*)d_out;

    zero_flags_kernel<<<1, 2 * NLAY>>>();
    conv_front_kernel<<<1, 256>>>(X, c1w, c1b, c2w, c2b);
    pack_weights_kernel<<<4 * 256 * 48, 256>>>(eih, ehh, dih, dhh);
    gru_wave_kernel<<<NLAY, 256>>>(ebih, ebhh, 0);
    gru_wave_kernel<<<NLAY, 256>>>(dbih, dbhh, 1);
    attn_fc_kernel<<<TSTEPS, 256>>>(fclw, fclb, out);
}

// round 11
// speedup vs baseline: 5.7072x; 5.7072x over previous
#include <cuda_runtime.h>
#include <cuda_bf16.h>

#define NLAY 256
#define TSTEPS 64
#define BATCH 4
#define HDIM 256
#define GDIM 768
#define NCLS 26

// Packed bf16-pair weights, uint4 per (kq, gate-row):
//   u32 component c of uint4 at [(l*32+kq)*768 + g] covers k = kq*8+2c (lo) and +1 (hi).
// Matrices: 0=enc_ih 1=enc_hh 2=dec_ih 3=dec_hh, each MATSZ u32s.
#define MATSZ ((size_t)NLAY * 32 * 768 * 4)
__device__ unsigned g_wpack4[4 * MATSZ];

// Sequence slots: enc block l reads g_seq[l], writes g_seq[l+1] (slot 256 = relu'd emb).
// dec block d reads g_seq[256] (d==0) else g_seq[d-1], writes g_seq[d].
__device__ float g_seq[NLAY + 1][TSTEPS][BATCH][HDIM];
__device__ int g_flags[2 * NLAY];

typedef unsigned long long u64;

__device__ __forceinline__ void unpk2(u64 v, float& lo, float& hi) {
    asm("mov.b64 {%0,%1},%2;" : "=f"(lo), "=f"(hi) : "l"(v));
}
__device__ __forceinline__ u64 expand_bf2(unsigned u) {
    float lo = __uint_as_float(u << 16);
    float hi = __uint_as_float(u & 0xffff0000u);
    u64 r; asm("mov.b64 %0,{%1,%2};" : "=l"(r) : "f"(lo), "f"(hi)); return r;
}
__device__ __forceinline__ void fma2(u64& acc, u64 a, u64 b) {
    asm("fma.rn.f32x2 %0,%1,%2,%0;" : "+l"(acc) : "l"(a), "l"(b));
}
__device__ __forceinline__ float sigm(float x) { return 1.f / (1.f + __expf(-x)); }

__global__ void zero_flags_kernel() { g_flags[threadIdx.x] = 0; }

// Pointwise convs collapse: seq[0][t][b][h] = X[b,0,2t]*A[h] + C[h]
__global__ void conv_front_kernel(const float* __restrict__ X,
                                  const float* __restrict__ c1w,
                                  const float* __restrict__ c1b,
                                  const float* __restrict__ c2w,
                                  const float* __restrict__ c2b) {
    __shared__ float xs[512];
    int j = threadIdx.x;
    xs[j] = X[j];
    xs[256 + j] = X[256 + j];
    __syncthreads();
    float A = 0.f, C = 0.f;
    for (int c = 0; c < 128; ++c) {
        float w2 = c2w[j * 128 + c];
        A += w2 * c1w[c];
        C += w2 * c1b[c];
    }
    C += c2b[j];
    for (int t = 0; t < TSTEPS; ++t)
        for (int b = 0; b < BATCH; ++b)
            g_seq[0][t][b][j] = xs[b * 128 + 2 * t] * A + C;
}

// Repack fp32 [l][g][k] -> uint4-friendly bf16-pair layout (see g_wpack4 comment).
// grid = 4 * 256 * 12 * 4 blocks of 256 threads.
__global__ void pack_weights_kernel(const float* __restrict__ eih,
                                    const float* __restrict__ ehh,
                                    const float* __restrict__ dih,
                                    const float* __restrict__ dhh) {
    __shared__ float tile[64][65];
    int bid = blockIdx.x;
    int m = bid / 12288;
    int r = bid % 12288;
    int l = r / 48;
    int r2 = r % 48;
    int gt = r2 / 4;   // g tile (64 wide)
    int kt = r2 % 4;   // k tile (64 wide)
    const float* src = (m == 0) ? eih : (m == 1) ? ehh : (m == 2) ? dih : dhh;
    int tid = threadIdx.x;
    #pragma unroll
    for (int i = 0; i < 16; ++i) {
        int idx = tid + i * 256;
        int gg = idx >> 6, kk = idx & 63;
        tile[gg][kk] = src[((size_t)l * GDIM + gt * 64 + gg) * HDIM + kt * 64 + kk];
    }
    __syncthreads();
    #pragma unroll
    for (int i = 0; i < 8; ++i) {
        int o = tid + i * 256;
        int gg = o & 63, kp = o >> 6;  // local k-pair 0..31
        float f0 = tile[gg][2 * kp];
        float f1 = tile[gg][2 * kp + 1];
        unsigned u = (unsigned)__bfloat16_as_ushort(__float2bfloat16(f0)) |
                     ((unsigned)__bfloat16_as_ushort(__float2bfloat16(f1)) << 16);
        size_t dst = (((size_t)l * 32 + kt * 8 + (kp >> 2)) * 768 + gt * 64 + gg) * 4 + (kp & 3);
        g_wpack4[(size_t)m * MATSZ + dst] = u;
    }
}

// Matvec: thread owns one gate row; acc[b] lanes = (even-k sum, odd-k sum) for batch b.
// v = float[4][256] in smem (broadcast loads).
__device__ __forceinline__ void matvec768(const uint4* __restrict__ wp,
                                          const float* __restrict__ v,
                                          u64 acc[4]) {
    #pragma unroll 4
    for (int kq = 0; kq < 32; ++kq) {
        uint4 w = *wp; wp += 768;
        const float* vk = v + kq * 8;
        ulonglong2 p0 = *(const ulonglong2*)(vk);
        ulonglong2 p1 = *(const ulonglong2*)(vk + 4);
        ulonglong2 p2 = *(const ulonglong2*)(vk + 256);
        ulonglong2 p3 = *(const ulonglong2*)(vk + 260);
        ulonglong2 p4 = *(const ulonglong2*)(vk + 512);
        ulonglong2 p5 = *(const ulonglong2*)(vk + 516);
        ulonglong2 p6 = *(const ulonglong2*)(vk + 768);
        ulonglong2 p7 = *(const ulonglong2*)(vk + 772);
        u64 wv;
        wv = expand_bf2(w.x);
        fma2(acc[0], wv, p0.x); fma2(acc[1], wv, p2.x);
        fma2(acc[2], wv, p4.x); fma2(acc[3], wv, p6.x);
        wv = expand_bf2(w.y);
        fma2(acc[0], wv, p0.y); fma2(acc[1], wv, p2.y);
        fma2(acc[2], wv, p4.y); fma2(acc[3], wv, p6.y);
        wv = expand_bf2(w.z);
        fma2(acc[0], wv, p1.x); fma2(acc[1], wv, p3.x);
        fma2(acc[2], wv, p5.x); fma2(acc[3], wv, p7.x);
        wv = expand_bf2(w.w);
        fma2(acc[0], wv, p1.y); fma2(acc[1], wv, p3.y);
        fma2(acc[2], wv, p5.y); fma2(acc[3], wv, p7.y);
    }
}

// Fused enc+dec wavefront: 512 blocks, block b = (b<256 ? enc layer b : dec layer b-256).
// Continuous flag chain 0..511 (dec block 0 consumes enc block 255's output).
// hh-matvec for t+1 runs AFTER publishing h_t, so the layer-hop latency is just
// wait + ih-matvec + gates.
__global__ void __launch_bounds__(768, 1)
gru_wave_kernel(const float* __restrict__ ebih, const float* __restrict__ ebhh,
                const float* __restrict__ dbih, const float* __restrict__ dbhh) {
    const int bid = blockIdx.x;
    const int tid = threadIdx.x;          // gate row 0..767
    const bool enc = bid < NLAY;
    const int l = bid & (NLAY - 1);

    __shared__ __align__(16) float xs[4][256];
    __shared__ __align__(16) float hs[4][256];
    __shared__ float gxs[4][768];
    __shared__ float ghs[4][768];

    const uint4* wih = (const uint4*)(g_wpack4 + (size_t)(enc ? 0 : 2) * MATSZ)
                       + ((size_t)l * 32 * 768 + tid);
    const uint4* whh = (const uint4*)(g_wpack4 + (size_t)(enc ? 1 : 3) * MATSZ)
                       + ((size_t)l * 32 * 768 + tid);

    const float bi = (enc ? ebih : dbih)[l * GDIM + tid];
    const float bh = (enc ? ebhh : dbhh)[l * GDIM + tid];

    const float* inp = enc ? &g_seq[l][0][0][0]
                           : (l == 0 ? &g_seq[NLAY][0][0][0] : &g_seq[l - 1][0][0][0]);
    float* outp = enc ? &g_seq[l + 1][0][0][0] : &g_seq[l][0][0][0];
    const bool relu_out = enc && (l == NLAY - 1);
    const int* prevflag = &g_flags[bid - 1];  // used only if bid>0
    int* myflag = &g_flags[bid];

    // h0 = 0 -> gh for t=0 is just bhh
    #pragma unroll
    for (int b = 0; b < 4; ++b) ghs[b][tid] = bh;
    float ho[4] = {0.f, 0.f, 0.f, 0.f};      // recurrent h, lives in threads tid<256

    for (int t = 0; t < TSTEPS; ++t) {
        // --- A: wait for producer, stage x_t ---
        if (tid == 0 && bid > 0) {
            int v;
            do {
                asm volatile("ld.acquire.gpu.global.u32 %0,[%1];"
                             : "=r"(v) : "l"(prevflag) : "memory");
                if (v > t) break;
                __nanosleep(40);
            } while (true);
        }
        __syncthreads();
        {
            const float* xt = inp + t * (BATCH * HDIM);
            ((float*)xs)[tid] = xt[tid];
            if (tid < 256) ((float*)xs)[768 + tid] = xt[768 + tid];
        }
        __syncthreads();

        // --- B: ih matvec ---
        {
            u64 acc[4] = {0ull, 0ull, 0ull, 0ull};
            matvec768(wih, &xs[0][0], acc);
            #pragma unroll
            for (int b = 0; b < 4; ++b) {
                float lo, hi; unpk2(acc[b], lo, hi);
                gxs[b][tid] = lo + hi + bi;
            }
        }
        __syncthreads();

        // --- C: gates (256 threads), publish h_t ---
        if (tid < 256) {
            #pragma unroll
            for (int b = 0; b < 4; ++b) {
                float r = sigm(gxs[b][tid] + ghs[b][tid]);
                float z = sigm(gxs[b][256 + tid] + ghs[b][256 + tid]);
                float n = tanhf(gxs[b][512 + tid] + r * ghs[b][512 + tid]);
                ho[b] = n + z * (ho[b] - n);            // (1-z)*n + z*h
                hs[b][tid] = ho[b];
                outp[t * (BATCH * HDIM) + b * HDIM + tid] =
                    relu_out ? fmaxf(ho[b], 0.f) : ho[b];
            }
        }
        __syncthreads();
        if (tid == 0) {
            asm volatile("st.release.gpu.global.u32 [%0],%1;"
                         :: "l"(myflag), "r"(t + 1) : "memory");
        }

        // --- D: hh matvec for t+1 (off the critical layer-hop path) ---
        if (t < TSTEPS - 1) {
            u64 acc[4] = {0ull, 0ull, 0ull, 0ull};
            matvec768(whh, &hs[0][0], acc);
            #pragma unroll
            for (int b = 0; b < 4; ++b) {
                float lo, hi; unpk2(acc[b], lo, hi);
                ghs[b][tid] = lo + hi + bh;
            }
        }
        // ghs consumed next iteration after two syncthreads; no extra sync needed.
    }
}

// Attention + FC + softmax tail. One block per timestep t.
__global__ void attn_fc_kernel(const float* __restrict__ fcl_w,
                               const float* __restrict__ fcl_b,
                               float* __restrict__ out) {
    const int t = blockIdx.x;
    const int tid = threadIdx.x;
    __shared__ float hid_s[BATCH][HDIM];
    __shared__ float sc[BATCH][TSTEPS];
    __shared__ float ctx[BATCH][HDIM];
    __shared__ float lg[BATCH][NCLS];

    #pragma unroll
    for (int b = 0; b < BATCH; ++b)
        hid_s[b][tid] = g_seq[NLAY - 1][t][b][tid];
    __syncthreads();

    int s = tid >> 2, q = tid & 3;
    #pragma unroll
    for (int b = 0; b < BATCH; ++b) {
        const float* e = &g_seq[NLAY][s][b][0];
        float acc = 0.f;
        for (int d = q * 64; d < q * 64 + 64; ++d) acc += hid_s[b][d] * e[d];
        acc += __shfl_xor_sync(0xffffffff, acc, 1);
        acc += __shfl_xor_sync(0xffffffff, acc, 2);
        if (q == 0) sc[b][s] = acc;
    }
    __syncthreads();

    if (tid < BATCH) {
        int b = tid;
        float m = -1e30f;
        for (int i = 0; i < TSTEPS; ++i) m = fmaxf(m, sc[b][i]);
        float sum = 0.f;
        for (int i = 0; i < TSTEPS; ++i) { float e = __expf(sc[b][i] - m); sc[b][i] = e; sum += e; }
        float inv = 1.f / sum;
        for (int i = 0; i < TSTEPS; ++i) sc[b][i] *= inv;
    }
    __syncthreads();

    #pragma unroll
    for (int b = 0; b < BATCH; ++b) {
        float acc = sc[b][0] * g_seq[NLAY][0][b][tid];
        for (int s2 = 0; s2 < TSTEPS - 1; ++s2)
            acc += sc[b][s2] * g_seq[NLAY][s2 + 1][b][tid];
        ctx[b][tid] = acc;
    }
    __syncthreads();

    if (tid < BATCH * NCLS) {
        int b = tid / NCLS, o = tid % NCLS;
        float acc = fcl_b[o];
        for (int f = 0; f < HDIM; ++f) acc += fcl_w[o * 2 * HDIM + f] * hid_s[b][f];
        for (int f = 0; f < HDIM; ++f) acc += fcl_w[o * 2 * HDIM + HDIM + f] * ctx[b][f];
        lg[b][o] = acc;
    }
    __syncthreads();

    if (tid < BATCH) {
        int b = tid;
        float m = -1e30f;
        for (int o = 0; o < NCLS; ++o) m = fmaxf(m, lg[b][o]);
        float ex[NCLS]; float sum = 0.f;
        for (int o = 0; o < NCLS; ++o) { ex[o] = __expf(lg[b][o] - m); sum += ex[o]; }
        float inv = 1.f / sum;
        for (int o = 0; o < NCLS; ++o)
            out[(t * BATCH + b) * NCLS + o] = ex[o] * inv;
    }
}

extern "C" void kernel_launch(void* const* d_in, const int* in_sizes, int n_in,
                              void* d_out, int out_size) {
    const float* X    = (const float*)d_in[0];
    const float* c1w  = (const float*)d_in[1];
    const float* c1b  = (const float*)d_in[2];
    const float* c2w  = (const float*)d_in[3];
    const float* c2b  = (const float*)d_in[4];
    const float* eih  = (const float*)d_in[5];
    const float* ehh  = (const float*)d_in[6];
    const float* ebih = (const float*)d_in[7];
    const float* ebhh = (const float*)d_in[8];
    const float* dih  = (const float*)d_in[9];
    const float* dhh  = (const float*)d_in[10];
    const float* dbih = (const float*)d_in[11];
    const float* dbhh = (const float*)d_in[12];
    const float* fclw = (const float*)d_in[13];
    const float* fclb = (const float*)d_in[14];
    float* out = (float*)d_out;

    zero_flags_kernel<<<1, 2 * NLAY>>>();
    conv_front_kernel<<<1, 256>>>(X, c1w, c1b, c2w, c2b);
    pack_weights_kernel<<<4 * 256 * 48, 256>>>(eih, ehh, dih, dhh);
    gru_wave_kernel<<<2 * NLAY, 768>>>(ebih, ebhh, dbih, dbhh);
    attn_fc_kernel<<<TSTEPS, 256>>>(fclw, fclb, out);
}

// round 12
// speedup vs baseline: 6.1436x; 1.0764x over previous
#include <cuda_runtime.h>
#include <cuda_bf16.h>

#define NLAY 256
#define TSTEPS 64
#define BATCH 4
#define HDIM 256
#define GDIM 768
#define NCLS 26

// Packed bf16-pair weights, uint4 per (kq, gate-row):
//   u32 component c of uint4 at [(l*32+kq)*768 + g] covers k = kq*8+2c (lo) and +1 (hi).
// Matrices: 0=enc_ih 1=enc_hh 2=dec_ih 3=dec_hh, each MATSZ u32s.
#define MATSZ ((size_t)NLAY * 32 * 768 * 4)
__device__ unsigned g_wpack4[4 * MATSZ];

// Sequence slots: enc layer l reads g_seq[l], writes g_seq[l+1] (slot 256 = relu'd emb).
// dec layer d reads g_seq[256] (d==0) else g_seq[d-1], writes g_seq[d].
__device__ float g_seq[NLAY + 1][TSTEPS][BATCH][HDIM];
// One flag per half-block: flags[bid], bid = pairIdx*2 + half.
__device__ int g_flags[4 * NLAY];

typedef unsigned long long u64;

__device__ __forceinline__ void unpk2(u64 v, float& lo, float& hi) {
    asm("mov.b64 {%0,%1},%2;" : "=f"(lo), "=f"(hi) : "l"(v));
}
__device__ __forceinline__ u64 expand_bf2(unsigned u) {
    float lo = __uint_as_float(u << 16);
    float hi = __uint_as_float(u & 0xffff0000u);
    u64 r; asm("mov.b64 %0,{%1,%2};" : "=l"(r) : "f"(lo), "f"(hi)); return r;
}
__device__ __forceinline__ void fma2(u64& acc, u64 a, u64 b) {
    asm("fma.rn.f32x2 %0,%1,%2,%0;" : "+l"(acc) : "l"(a), "l"(b));
}
__device__ __forceinline__ float sigm(float x) { return 1.f / (1.f + __expf(-x)); }

// Weight loads: EL = keep in L1 (critical-path ih), CS = streaming (hh).
template <int CS>
__device__ __forceinline__ uint4 ldw(const uint4* p) {
    uint4 r;
    if (CS == 0)
        asm("ld.global.nc.L1::evict_last.v4.u32 {%0,%1,%2,%3},[%4];"
            : "=r"(r.x), "=r"(r.y), "=r"(r.z), "=r"(r.w) : "l"(p));
    else
        asm("ld.global.cs.v4.u32 {%0,%1,%2,%3},[%4];"
            : "=r"(r.x), "=r"(r.y), "=r"(r.z), "=r"(r.w) : "l"(p));
    return r;
}

__global__ void zero_flags_kernel() { g_flags[threadIdx.x] = 0; }

// Pointwise convs collapse: seq[0][t][b][h] = X[b,0,2t]*A[h] + C[h]
__global__ void conv_front_kernel(const float* __restrict__ X,
                                  const float* __restrict__ c1w,
                                  const float* __restrict__ c1b,
                                  const float* __restrict__ c2w,
                                  const float* __restrict__ c2b) {
    __shared__ float xs[512];
    int j = threadIdx.x;
    xs[j] = X[j];
    xs[256 + j] = X[256 + j];
    __syncthreads();
    float A = 0.f, C = 0.f;
    for (int c = 0; c < 128; ++c) {
        float w2 = c2w[j * 128 + c];
        A += w2 * c1w[c];
        C += w2 * c1b[c];
    }
    C += c2b[j];
    for (int t = 0; t < TSTEPS; ++t)
        for (int b = 0; b < BATCH; ++b)
            g_seq[0][t][b][j] = xs[b * 128 + 2 * t] * A + C;
}

// Repack fp32 [l][g][k] -> uint4-friendly bf16-pair layout (see g_wpack4 comment).
__global__ void pack_weights_kernel(const float* __restrict__ eih,
                                    const float* __restrict__ ehh,
                                    const float* __restrict__ dih,
                                    const float* __restrict__ dhh) {
    __shared__ float tile[64][65];
    int bid = blockIdx.x;
    int m = bid / 12288;
    int r = bid % 12288;
    int l = r / 48;
    int r2 = r % 48;
    int gt = r2 / 4;
    int kt = r2 % 4;
    const float* src = (m == 0) ? eih : (m == 1) ? ehh : (m == 2) ? dih : dhh;
    int tid = threadIdx.x;
    #pragma unroll
    for (int i = 0; i < 16; ++i) {
        int idx = tid + i * 256;
        int gg = idx >> 6, kk = idx & 63;
        tile[gg][kk] = src[((size_t)l * GDIM + gt * 64 + gg) * HDIM + kt * 64 + kk];
    }
    __syncthreads();
    #pragma unroll
    for (int i = 0; i < 8; ++i) {
        int o = tid + i * 256;
        int gg = o & 63, kp = o >> 6;
        float f0 = tile[gg][2 * kp];
        float f1 = tile[gg][2 * kp + 1];
        unsigned u = (unsigned)__bfloat16_as_ushort(__float2bfloat16(f0)) |
                     ((unsigned)__bfloat16_as_ushort(__float2bfloat16(f1)) << 16);
        size_t dst = (((size_t)l * 32 + kt * 8 + (kp >> 2)) * 768 + gt * 64 + gg) * 4 + (kp & 3);
        g_wpack4[(size_t)m * MATSZ + dst] = u;
    }
}

// Matvec for one gate row over 4 batches; acc[b] lanes = (even-k sum, odd-k sum).
template <int CS>
__device__ __forceinline__ void matvec768(const uint4* __restrict__ wp,
                                          const float* __restrict__ v,
                                          u64 acc[4]) {
    #pragma unroll 4
    for (int kq = 0; kq < 32; ++kq) {
        uint4 w = ldw<CS>(wp); wp += 768;
        const float* vk = v + kq * 8;
        ulonglong2 p0 = *(const ulonglong2*)(vk);
        ulonglong2 p1 = *(const ulonglong2*)(vk + 4);
        ulonglong2 p2 = *(const ulonglong2*)(vk + 256);
        ulonglong2 p3 = *(const ulonglong2*)(vk + 260);
        ulonglong2 p4 = *(const ulonglong2*)(vk + 512);
        ulonglong2 p5 = *(const ulonglong2*)(vk + 516);
        ulonglong2 p6 = *(const ulonglong2*)(vk + 768);
        ulonglong2 p7 = *(const ulonglong2*)(vk + 772);
        u64 wv;
        wv = expand_bf2(w.x);
        fma2(acc[0], wv, p0.x); fma2(acc[1], wv, p2.x);
        fma2(acc[2], wv, p4.x); fma2(acc[3], wv, p6.x);
        wv = expand_bf2(w.y);
        fma2(acc[0], wv, p0.y); fma2(acc[1], wv, p2.y);
        fma2(acc[2], wv, p4.y); fma2(acc[3], wv, p6.y);
        wv = expand_bf2(w.z);
        fma2(acc[0], wv, p1.x); fma2(acc[1], wv, p3.x);
        fma2(acc[2], wv, p5.x); fma2(acc[3], wv, p7.x);
        wv = expand_bf2(w.w);
        fma2(acc[0], wv, p1.y); fma2(acc[1], wv, p3.y);
        fma2(acc[2], wv, p5.y); fma2(acc[3], wv, p7.y);
    }
}

// Half-layer wavefront: 1024 blocks = 512 layer-pairs x 2 halves, 384 threads.
// Half owns hidden units [half*128, half*128+128): thread tid -> gate gi=tid/128
// (0=r,1=z,2=n), unit u=tid%128, global weight row = gi*256 + half*128 + u.
// Critical hop = wait prev-layer flags -> stage x -> ih matvec -> gates -> publish.
// hh matvec runs after publishing (off the hop path), using own h + peer h from L2.
__global__ void __launch_bounds__(384, 2)
gru_wave_kernel(const float* __restrict__ ebih, const float* __restrict__ ebhh,
                const float* __restrict__ dbih, const float* __restrict__ dbhh) {
    const int bid = blockIdx.x;
    const int tid = threadIdx.x;
    const int pairIdx = bid >> 1;         // 0..511 global layer index (enc then dec)
    const int half = bid & 1;
    const bool enc = pairIdx < NLAY;
    const int l = pairIdx & (NLAY - 1);
    const int u = tid & 127;
    const int gi = tid >> 7;
    const int row = gi * 256 + half * 128 + u;

    __shared__ __align__(16) float xs[4][256];
    __shared__ __align__(16) float hs[4][256];
    __shared__ float gxs[4][384];
    __shared__ float ghs[4][384];

    const uint4* wih = (const uint4*)(g_wpack4 + (size_t)(enc ? 0 : 2) * MATSZ)
                       + ((size_t)l * 32 * 768 + row);
    const uint4* whh = (const uint4*)(g_wpack4 + (size_t)(enc ? 1 : 3) * MATSZ)
                       + ((size_t)l * 32 * 768 + row);

    const float bi = (enc ? ebih : dbih)[l * GDIM + row];
    const float bh = (enc ? ebhh : dbhh)[l * GDIM + row];

    const float* inp = enc ? &g_seq[l][0][0][0]
                           : (l == 0 ? &g_seq[NLAY][0][0][0] : &g_seq[l - 1][0][0][0]);
    float* outp = enc ? &g_seq[l + 1][0][0][0] : &g_seq[l][0][0][0];
    const bool relu_out = enc && (l == NLAY - 1);
    const int* pf0 = &g_flags[2 * (pairIdx - 1)];      // valid only if pairIdx>0
    const int* pf1 = &g_flags[2 * (pairIdx - 1) + 1];
    const int* peerflag = &g_flags[bid ^ 1];
    int* myflag = &g_flags[bid];

    #pragma unroll
    for (int b = 0; b < 4; ++b) ghs[b][tid] = bh;      // h0 = 0 -> gh = bhh
    float ho[4] = {0.f, 0.f, 0.f, 0.f};                // live in threads tid<128

    for (int t = 0; t < TSTEPS; ++t) {
        // --- A: wait for both halves of the previous layer ---
        if (tid == 0 && pairIdx > 0) {
            int v;
            do {
                asm volatile("ld.acquire.gpu.global.u32 %0,[%1];"
                             : "=r"(v) : "l"(pf0) : "memory");
                if (v > t) break;
                __nanosleep(20);
            } while (true);
            do {
                asm volatile("ld.acquire.gpu.global.u32 %0,[%1];"
                             : "=r"(v) : "l"(pf1) : "memory");
                if (v > t) break;
                __nanosleep(20);
            } while (true);
        }
        __syncthreads();

        // stage x_t (full 4x256)
        {
            const float* xt = inp + t * (BATCH * HDIM);
            for (int i = tid; i < 1024; i += 384) ((float*)xs)[i] = xt[i];
        }
        __syncthreads();

        // --- B: ih matvec (critical path; L1-persistent weights) ---
        {
            u64 acc[4] = {0ull, 0ull, 0ull, 0ull};
            matvec768<0>(wih, &xs[0][0], acc);
            #pragma unroll
            for (int b = 0; b < 4; ++b) {
                float lo, hi; unpk2(acc[b], lo, hi);
                gxs[b][tid] = lo + hi + bi;
            }
        }
        __syncthreads();

        // --- C: gates for own 128 units, publish own h half ---
        if (tid < 128) {
            #pragma unroll
            for (int b = 0; b < 4; ++b) {
                float r = sigm(gxs[b][u] + ghs[b][u]);
                float z = sigm(gxs[b][128 + u] + ghs[b][128 + u]);
                float n = tanhf(gxs[b][256 + u] + r * ghs[b][256 + u]);
                ho[b] = n + z * (ho[b] - n);           // (1-z)*n + z*h
                hs[b][half * 128 + u] = ho[b];
                outp[t * (BATCH * HDIM) + b * HDIM + half * 128 + u] =
                    relu_out ? fmaxf(ho[b], 0.f) : ho[b];
            }
        }
        __syncthreads();
        if (tid == 0) {
            asm volatile("st.release.gpu.global.u32 [%0],%1;"
                         :: "l"(myflag), "r"(t + 1) : "memory");
        }

        // --- D: hh matvec for t+1 (off the hop path) ---
        if (t < TSTEPS - 1) {
            // fetch peer half of h_t
            if (tid == 0) {
                int v;
                do {
                    asm volatile("ld.acquire.gpu.global.u32 %0,[%1];"
                                 : "=r"(v) : "l"(peerflag) : "memory");
                    if (v > t) break;
                    __nanosleep(20);
                } while (true);
            }
            __syncthreads();
            {
                int ph = (half ^ 1) * 128;
                for (int i = tid; i < 512; i += 384) {
                    int b = i >> 7, uu = i & 127;
                    hs[b][ph + uu] = outp[t * (BATCH * HDIM) + b * HDIM + ph + uu];
                }
            }
            __syncthreads();
            u64 acc[4] = {0ull, 0ull, 0ull, 0ull};
            matvec768<1>(whh, &hs[0][0], acc);
            #pragma unroll
            for (int b = 0; b < 4; ++b) {
                float lo, hi; unpk2(acc[b], lo, hi);
                ghs[b][tid] = lo + hi + bh;
            }
        }
        // ghs consumed next iteration after syncs in phases A/B.
    }
}

// Attention + FC + softmax tail. One block per timestep t.
__global__ void attn_fc_kernel(const float* __restrict__ fcl_w,
                               const float* __restrict__ fcl_b,
                               float* __restrict__ out) {
    const int t = blockIdx.x;
    const int tid = threadIdx.x;
    __shared__ float hid_s[BATCH][HDIM];
    __shared__ float sc[BATCH][TSTEPS];
    __shared__ float ctx[BATCH][HDIM];
    __shared__ float lg[BATCH][NCLS];

    #pragma unroll
    for (int b = 0; b < BATCH; ++b)
        hid_s[b][tid] = g_seq[NLAY - 1][t][b][tid];
    __syncthreads();

    int s = tid >> 2, q = tid & 3;
    #pragma unroll
    for (int b = 0; b < BATCH; ++b) {
        const float* e = &g_seq[NLAY][s][b][0];
        float acc = 0.f;
        for (int d = q * 64; d < q * 64 + 64; ++d) acc += hid_s[b][d] * e[d];
        acc += __shfl_xor_sync(0xffffffff, acc, 1);
        acc += __shfl_xor_sync(0xffffffff, acc, 2);
        if (q == 0) sc[b][s] = acc;
    }
    __syncthreads();

    if (tid < BATCH) {
        int b = tid;
        float m = -1e30f;
        for (int i = 0; i < TSTEPS; ++i) m = fmaxf(m, sc[b][i]);
        float sum = 0.f;
        for (int i = 0; i < TSTEPS; ++i) { float e = __expf(sc[b][i] - m); sc[b][i] = e; sum += e; }
        float inv = 1.f / sum;
        for (int i = 0; i < TSTEPS; ++i) sc[b][i] *= inv;
    }
    __syncthreads();

    #pragma unroll
    for (int b = 0; b < BATCH; ++b) {
        float acc = sc[b][0] * g_seq[NLAY][0][b][tid];
        for (int s2 = 0; s2 < TSTEPS - 1; ++s2)
            acc += sc[b][s2] * g_seq[NLAY][s2 + 1][b][tid];
        ctx[b][tid] = acc;
    }
    __syncthreads();

    if (tid < BATCH * NCLS) {
        int b = tid / NCLS, o = tid % NCLS;
        float acc = fcl_b[o];
        for (int f = 0; f < HDIM; ++f) acc += fcl_w[o * 2 * HDIM + f] * hid_s[b][f];
        for (int f = 0; f < HDIM; ++f) acc += fcl_w[o * 2 * HDIM + HDIM + f] * ctx[b][f];
        lg[b][o] = acc;
    }
    __syncthreads();

    if (tid < BATCH) {
        int b = tid;
        float m = -1e30f;
        for (int o = 0; o < NCLS; ++o) m = fmaxf(m, lg[b][o]);
        float ex[NCLS]; float sum = 0.f;
        for (int o = 0; o < NCLS; ++o) { ex[o] = __expf(lg[b][o] - m); sum += ex[o]; }
        float inv = 1.f / sum;
        for (int o = 0; o < NCLS; ++o)
            out[(t * BATCH + b) * NCLS + o] = ex[o] * inv;
    }
}

extern "C" void kernel_launch(void* const* d_in, const int* in_sizes, int n_in,
                              void* d_out, int out_size) {
    const float* X    = (const float*)d_in[0];
    const float* c1w  = (const float*)d_in[1];
    const float* c1b  = (const float*)d_in[2];
    const float* c2w  = (const float*)d_in[3];
    const float* c2b  = (const float*)d_in[4];
    const float* eih  = (const float*)d_in[5];
    const float* ehh  = (const float*)d_in[6];
    const float* ebih = (const float*)d_in[7];
    const float* ebhh = (const float*)d_in[8];
    const float* dih  = (const float*)d_in[9];
    const float* dhh  = (const float*)d_in[10];
    const float* dbih = (const float*)d_in[11];
    const float* dbhh = (const float*)d_in[12];
    const float* fclw = (const float*)d_in[13];
    const float* fclb = (const float*)d_in[14];
    float* out = (float*)d_out;

    zero_flags_kernel<<<1, 4 * NLAY>>>();
    conv_front_kernel<<<1, 256>>>(X, c1w, c1b, c2w, c2b);
    pack_weights_kernel<<<4 * 256 * 48, 256>>>(eih, ehh, dih, dhh);
    gru_wave_kernel<<<4 * NLAY, 384>>>(ebih, ebhh, dbih, dbhh);
    attn_fc_kernel<<<TSTEPS, 256>>>(fclw, fclb, out);
}